// round 8
// baseline (speedup 1.0000x reference)
#include <cuda_runtime.h>
#include <cuda_bf16.h>
#include <math.h>
#include <stdint.h>

#define F_DIM 256
#define N_MAX 200000
#define B_MAX 4000

// ---- scratch (device globals: allocation-free) ----
__device__ float g_kq[B_MAX * F_DIM];
__device__ float g_kb[B_MAX];
__device__ float g_vmol[B_MAX * F_DIM];
__device__ float g_a[N_MAX];
__device__ float g_part[(N_MAX + 7) / 8];
__device__ float g_inv[1];
__device__ float g_H[(size_t)N_MAX * F_DIM];
__device__ float g_Y[(size_t)N_MAX * F_DIM];
__device__ __nv_bfloat16 g_Whi[5 * F_DIM * F_DIM];
__device__ __nv_bfloat16 g_Wlo[5 * F_DIM * F_DIM];

// ============================================================
// helpers
// ============================================================
__device__ __forceinline__ uint32_t smem_u32(const void* p) {
    uint32_t a;
    asm("{ .reg .u64 t; cvta.to.shared.u64 t, %1; cvt.u32.u64 %0, t; }" : "=r"(a) : "l"(p));
    return a;
}
#define LDSM_X4(r, addr) \
    asm volatile("ldmatrix.sync.aligned.m8n8.x4.shared.b16 {%0,%1,%2,%3}, [%4];" \
        : "=r"((r)[0]), "=r"((r)[1]), "=r"((r)[2]), "=r"((r)[3]) : "r"(addr))
#define MMA_BF16(c, a, b) \
    asm volatile("mma.sync.aligned.m16n8k16.row.col.f32.bf16.bf16.f32 " \
        "{%0,%1,%2,%3}, {%4,%5,%6,%7}, {%8,%9}, {%0,%1,%2,%3};" \
        : "+f"((c)[0]), "+f"((c)[1]), "+f"((c)[2]), "+f"((c)[3]) \
        : "r"((a)[0]), "r"((a)[1]), "r"((a)[2]), "r"((a)[3]), "r"((b)[0]), "r"((b)[1]))
#define CP_ASYNC16(dst, src) \
    asm volatile("cp.async.cg.shared.global [%0], [%1], 16;" :: "r"(dst), "l"(src))
#define CP_COMMIT() asm volatile("cp.async.commit_group;" ::: "memory")
#define CP_WAIT0()  asm volatile("cp.async.wait_group 0;" ::: "memory")

__device__ __forceinline__ uint32_t pack2bf(float x, float y) {
    __nv_bfloat16 bx = __float2bfloat16_rn(x), by = __float2bfloat16_rn(y);
    return ((uint32_t)__bfloat16_as_ushort(by) << 16) | (uint32_t)__bfloat16_as_ushort(bx);
}

// ============================================================
// K1: per-molecule prep (unchanged)
// ============================================================
__global__ void mol_prep(const float* __restrict__ E, const float* __restrict__ Wq,
                         const float* __restrict__ bq, const float* __restrict__ Wk,
                         const float* __restrict__ Wv, int B) {
    __shared__ float k_s[16][F_DIM];
    __shared__ float e_s[16][2], en_s[16][2];
    __shared__ float red[8];
    int tid = threadIdx.x;
    int b0  = blockIdx.x * 16;

    if (tid < 16) {
        int mol = b0 + tid;
        float Ev = (mol < B) ? E[mol] : 0.f;
        float e0 = fmaxf(Ev, 0.f), e1 = fmaxf(-Ev, 0.f);
        e_s[tid][0]  = e0;             e_s[tid][1]  = e1;
        en_s[tid][0] = fminf(e0, 1.f); en_s[tid][1] = fminf(e1, 1.f);
    }
    __syncthreads();

    float wk0 = Wk[tid * 2], wk1 = Wk[tid * 2 + 1];
    float wv0 = Wv[tid * 2], wv1 = Wv[tid * 2 + 1];
    #pragma unroll
    for (int b = 0; b < 16; b++) {
        float kv = en_s[b][0] * wk0 + en_s[b][1] * wk1;
        k_s[b][tid] = kv;
        int mol = b0 + b;
        if (mol < B) g_vmol[mol * F_DIM + tid] = e_s[b][0] * wv0 + e_s[b][1] * wv1;
    }
    __syncthreads();

    float acc[16];
    #pragma unroll
    for (int b = 0; b < 16; b++) acc[b] = 0.f;
    for (int f = 0; f < F_DIM; f++) {
        float w = Wq[f * F_DIM + tid];
        #pragma unroll
        for (int b = 0; b < 16; b++) acc[b] += k_s[b][f] * w;
    }
    #pragma unroll
    for (int b = 0; b < 16; b++) {
        int mol = b0 + b;
        if (mol < B) g_kq[mol * F_DIM + tid] = acc[b];
    }

    float bqv = bq[tid];
    int lane = tid & 31, wid = tid >> 5;
    for (int b = 0; b < 16; b++) {
        float v = k_s[b][tid] * bqv;
        #pragma unroll
        for (int o = 16; o > 0; o >>= 1) v += __shfl_down_sync(0xffffffffu, v, o);
        if (lane == 0) red[wid] = v;
        __syncthreads();
        if (tid == 0) {
            float s = 0.f;
            #pragma unroll
            for (int w = 0; w < 8; w++) s += red[w];
            int mol = b0 + b;
            if (mol < B) g_kb[mol] = s;
        }
        __syncthreads();
    }
}

// ============================================================
// K2: per-atom score (unchanged)
// ============================================================
__global__ void atom_score(const float* __restrict__ x, const int* __restrict__ idx, int N) {
    __shared__ float wsum[8];
    int tid = threadIdx.x, lane = tid & 31, wid = tid >> 5;
    int n = blockIdx.x * 8 + wid;
    float a = 0.f;
    if (n < N) {
        int m = idx[n];
        const float* xr = x    + (size_t)n * F_DIM;
        const float* kq = g_kq + (size_t)m * F_DIM;
        float s = 0.f;
        #pragma unroll
        for (int j = 0; j < 8; j++) { int c = lane + j * 32; s += xr[c] * kq[c]; }
        #pragma unroll
        for (int o = 16; o > 0; o >>= 1) s += __shfl_down_sync(0xffffffffu, s, o);
        if (lane == 0) {
            float d = (s + g_kb[m]) * 0.0625f;
            a = fmaxf(d, 0.f) + log1pf(expf(-fabsf(d)));
            g_a[n] = a;
        }
    }
    if (lane == 0) wsum[wid] = a;
    __syncthreads();
    if (tid == 0) {
        float t = 0.f;
        #pragma unroll
        for (int w = 0; w < 8; w++) t += wsum[w];
        g_part[blockIdx.x] = t;
    }
}

// ============================================================
// K3: fused normalization + weight split (one launch)
// ============================================================
__global__ void prep_misc(const float* __restrict__ W1, const float* __restrict__ W2,
                          const float* __restrict__ Wout, int R, int nparts) {
    int tid = threadIdx.x;
    if (blockIdx.x == 0) {
        __shared__ float red[256];
        float s = 0.f;
        for (int i = tid; i < nparts; i += 256) s += g_part[i];
        red[tid] = s;
        __syncthreads();
        for (int o = 128; o > 0; o >>= 1) {
            if (tid < o) red[tid] += red[tid + o];
            __syncthreads();
        }
        if (tid == 0) g_inv[0] = 1.f / (red[0] + 1e-8f);
        return;
    }
    int i = (blockIdx.x - 1) * 256 + tid;
    int total = (2 * R + 1) * F_DIM * F_DIM;
    if (i >= total) return;
    int slot = i >> 16, j = i & 65535;
    const float* src = (slot == 2 * R) ? (Wout + j)
                     : (((slot & 1) ? W2 : W1) + (size_t)(slot >> 1) * 65536 + j);
    float w = *src;
    __nv_bfloat16 hi = __float2bfloat16_rn(w);
    __nv_bfloat16 lo = __float2bfloat16_rn(w - __bfloat162float(hi));
    g_Whi[i] = hi;
    g_Wlo[i] = lo;
}

// ============================================================
// K4: warp-mma bf16 split-3 GEMM.
// CTA: 128 rows x 128 cols, 256 threads (8 warps: 2m x 4n, warp 64x32).
// BK=32, cp.async B, double-buffered; 2 CTAs/SM (max smem carveout set host-side).
// ============================================================
#define BK 32
#define NCHUNK (F_DIM / BK)
#define PITCH 80
#define A_TILE (128 * PITCH)
#define B_TILE (128 * PITCH)
#define SM_AL   0
#define SM_BE   1024
#define SM_RSC  2048
#define SM_RM   2560
#define SM_A    3072
#define SM_B    (3072 + 4 * A_TILE)
#define SM_TOTAL (SM_B + 4 * B_TILE)       // 84992 bytes

__global__ void __launch_bounds__(256, 2) gemm_tc(
    int Acode, int slot, const float* __restrict__ al, const float* __restrict__ be,
    int Ccode, int accmode, float* outp, const int* __restrict__ idx, int Nrows) {
    extern __shared__ char smem[];
    const uint32_t sb = smem_u32(smem);
    const int tid  = threadIdx.x;
    const int lane = tid & 31, wrp = tid >> 5;
    const int warpM = wrp >> 2, warpN = wrp & 3;   // 2 x 4
    const int m0 = blockIdx.x * 128;
    const int n0 = blockIdx.y * 128;

    float* sAl  = (float*)(smem + SM_AL);
    float* sBe  = (float*)(smem + SM_BE);
    float* sRsc = (float*)(smem + SM_RSC);
    int*   sRm  = (int*)  (smem + SM_RM);

    if (tid < 256) { sAl[tid] = al[tid]; sBe[tid] = be[tid]; }
    {
        int r = tid >> 1;
        if ((tid & 1) == 0) {
            int grow = m0 + r;
            if (grow < Nrows) { sRsc[r] = g_a[grow] * g_inv[0]; sRm[r] = idx[grow]; }
            else              { sRsc[r] = 0.f; sRm[r] = 0; }
        }
    }
    __syncthreads();

    const float* Asrc = (Acode == 0) ? g_H : (Acode == 1) ? g_Y : (const float*)0;
    const __nv_bfloat16* Bbase[2] = { g_Whi + (size_t)slot * 65536 + (size_t)n0 * F_DIM,
                                      g_Wlo + (size_t)slot * 65536 + (size_t)n0 * F_DIM };

    float acc[4][4][4];
    #pragma unroll
    for (int i = 0; i < 4; i++)
        #pragma unroll
        for (int j = 0; j < 4; j++)
            #pragma unroll
            for (int l = 0; l < 4; l++) acc[i][j][l] = 0.f;

    auto cpB = [&](int c, int db) {
        const int k0 = c * BK;
        #pragma unroll
        for (int i = 0; i < 4; i++) {
            int t   = tid + i * 256;
            int sp  = t >> 9;
            int w   = t & 511;
            int row = w >> 2, c16 = w & 3;
            const __nv_bfloat16* src = Bbase[sp] + (size_t)row * F_DIM + k0 + c16 * 8;
            uint32_t dst = sb + SM_B + (uint32_t)(db * 2 + sp) * B_TILE
                         + (uint32_t)row * PITCH + c16 * 16;
            CP_ASYNC16(dst, src);
        }
        CP_COMMIT();
    };

    float4 pa[4];
    auto prefetchA = [&](int c) {
        const int k0 = c * BK;
        #pragma unroll
        for (int i = 0; i < 4; i++) {
            int q = tid + i * 256;
            int r = q >> 3, c4 = q & 7;
            int grow = m0 + r;
            float4 v = make_float4(0.f, 0.f, 0.f, 0.f);
            if (grow < Nrows) {
                if (Acode == 3)
                    v = ((const float4*)(g_vmol + (size_t)sRm[r] * F_DIM + k0))[c4];
                else
                    v = ((const float4*)(Asrc + (size_t)grow * F_DIM + k0))[c4];
            }
            pa[i] = v;
        }
    };
    auto stsA = [&](int c, int db) {
        const int k0 = c * BK;
        char* ahd = smem + SM_A + (size_t)(db * 2 + 0) * A_TILE;
        char* ald = smem + SM_A + (size_t)(db * 2 + 1) * A_TILE;
        #pragma unroll
        for (int i = 0; i < 4; i++) {
            int q = tid + i * 256;
            int r = q >> 3, c4 = q & 7;
            float vals[4] = {pa[i].x, pa[i].y, pa[i].z, pa[i].w};
            float sc = (Acode == 3) ? sRsc[r] : 1.f;
            float hi[4], lo[4];
            #pragma unroll
            for (int j = 0; j < 4; j++) {
                int col = k0 + c4 * 4 + j;
                float xv = sc * vals[j];
                float s  = sBe[col] * xv;
                float sw = sAl[col] * s * (1.f / (1.f + __expf(-s)));
                __nv_bfloat16 bh = __float2bfloat16_rn(sw);
                hi[j] = __bfloat162float(bh);
                lo[j] = sw - hi[j];
            }
            uint32_t o = (uint32_t)(r * PITCH + c4 * 8);
            *(uint2*)(ahd + o) = make_uint2(pack2bf(hi[0], hi[1]), pack2bf(hi[2], hi[3]));
            *(uint2*)(ald + o) = make_uint2(pack2bf(lo[0], lo[1]), pack2bf(lo[2], lo[3]));
        }
    };

    cpB(0, 0);
    prefetchA(0);
    stsA(0, 0);
    CP_WAIT0();
    __syncthreads();

    const uint32_t aAddr0 = sb + SM_A + (uint32_t)(warpM * 64 + (lane & 15)) * PITCH
                          + ((lane >> 4) * 16);
    const uint32_t bAddr0 = sb + SM_B
                          + (uint32_t)(warpN * 32 + (lane & 7) + ((lane >> 4) << 3)) * PITCH
                          + (((lane >> 3) & 1) * 16);

    for (int c = 0; c < NCHUNK; c++) {
        const int db = c & 1;
        if (c + 1 < NCHUNK) { cpB(c + 1, db ^ 1); prefetchA(c + 1); }

        const uint32_t aB = aAddr0 + (uint32_t)(db * 2) * A_TILE;
        const uint32_t bB = bAddr0 + (uint32_t)(db * 2) * B_TILE;
        #pragma unroll
        for (int s = 0; s < 2; s++) {
            uint32_t bh[4][2], bl[4][2];
            #pragma unroll
            for (int ntp = 0; ntp < 2; ntp++) {
                uint32_t t4[4];
                uint32_t ab = bB + ntp * (16 * PITCH) + s * 32;
                LDSM_X4(t4, ab);
                bh[2*ntp][0] = t4[0]; bh[2*ntp][1] = t4[1];
                bh[2*ntp+1][0] = t4[2]; bh[2*ntp+1][1] = t4[3];
                LDSM_X4(t4, ab + B_TILE);
                bl[2*ntp][0] = t4[0]; bl[2*ntp][1] = t4[1];
                bl[2*ntp+1][0] = t4[2]; bl[2*ntp+1][1] = t4[3];
            }
            #pragma unroll
            for (int mt = 0; mt < 4; mt++) {
                uint32_t aa = aB + mt * (16 * PITCH) + s * 32;
                uint32_t ah[4], alr[4];
                LDSM_X4(ah, aa);
                LDSM_X4(alr, aa + A_TILE);
                #pragma unroll
                for (int nt = 0; nt < 4; nt++) {
                    MMA_BF16(acc[mt][nt], ah,  bh[nt]);
                    MMA_BF16(acc[mt][nt], ah,  bl[nt]);
                    MMA_BF16(acc[mt][nt], alr, bh[nt]);
                }
            }
        }
        if (c + 1 < NCHUNK) { stsA(c + 1, db ^ 1); CP_WAIT0(); }
        __syncthreads();
    }

    // ---- epilogue ----
    float* Cp = (Ccode == 0) ? g_H : (Ccode == 1) ? g_Y : outp;
    const int rbase = warpM * 64 + (lane >> 2);
    const int cbase = n0 + warpN * 32 + (lane & 3) * 2;
    #pragma unroll
    for (int mt = 0; mt < 4; mt++) {
        #pragma unroll
        for (int rh = 0; rh < 2; rh++) {
            int lr = rbase + mt * 16 + rh * 8;
            int grow = m0 + lr;
            if (grow >= Nrows) continue;
            float* cp = Cp + (size_t)grow * F_DIM + cbase;
            float sc = 0.f; const float* vp = 0;
            if (accmode == 2) { sc = sRsc[lr]; vp = g_vmol + (size_t)sRm[lr] * F_DIM + cbase; }
            #pragma unroll
            for (int nt = 0; nt < 4; nt++) {
                float v0 = acc[mt][nt][rh * 2 + 0];
                float v1 = acc[mt][nt][rh * 2 + 1];
                float* dst = cp + nt * 8;
                if (accmode == 1) {
                    float2 o = *(float2*)dst;
                    v0 += o.x; v1 += o.y;
                } else if (accmode == 2) {
                    float2 o = *(const float2*)(vp + nt * 8);
                    v0 += sc * o.x; v1 += sc * o.y;
                }
                *(float2*)dst = make_float2(v0, v1);
            }
        }
    }
}

// ============================================================
extern "C" void kernel_launch(void* const* d_in, const int* in_sizes, int n_in,
                              void* d_out, int out_size) {
    const float* x    = (const float*)d_in[0];
    const float* E    = (const float*)d_in[1];
    const int*   asi  = (const int*)  d_in[2];
    const float* Wq   = (const float*)d_in[3];
    const float* bq   = (const float*)d_in[4];
    const float* Wk   = (const float*)d_in[5];
    const float* Wv   = (const float*)d_in[6];
    const float* W1   = (const float*)d_in[7];
    const float* W2   = (const float*)d_in[8];
    const float* a1   = (const float*)d_in[9];
    const float* b1   = (const float*)d_in[10];
    const float* a2   = (const float*)d_in[11];
    const float* b2   = (const float*)d_in[12];
    const float* oa   = (const float*)d_in[13];
    const float* ob   = (const float*)d_in[14];
    const float* Wout = (const float*)d_in[15];

    int B = in_sizes[1];
    int N = in_sizes[2];
    int R = in_sizes[7] / (F_DIM * F_DIM);
    float* out = (float*)d_out;

    // KEY FIX: request the maximum shared-memory carveout so TWO 85KB CTAs
    // can be resident per SM (default carveout tier fit only one).
    cudaFuncSetAttribute(gemm_tc, cudaFuncAttributeMaxDynamicSharedMemorySize, SM_TOTAL);
    cudaFuncSetAttribute(gemm_tc, cudaFuncAttributePreferredSharedMemoryCarveout, 100);

    mol_prep<<<(B + 15) / 16, 256>>>(E, Wq, bq, Wk, Wv, B);          // 0

    int gS = (N + 7) / 8;
    atom_score<<<gS, 256>>>(x, asi, N);                               // 1

    int wblocks = ((2 * R + 1) * F_DIM * F_DIM + 255) / 256;
    prep_misc<<<1 + wblocks, 256>>>(W1, W2, Wout, R, gS);             // 2

    dim3 grid((N + 127) / 128, 2);
    gemm_tc<<<grid, 256, SM_TOTAL>>>(3, 0, a1, b1, 1, 0, out, asi, N);   // 3
    gemm_tc<<<grid, 256, SM_TOTAL>>>(1, 1, a2, b2, 0, 2, out, asi, N);   // 4
    for (int i = 1; i < R; i++) {                                        // 5, 6
        gemm_tc<<<grid, 256, SM_TOTAL>>>(0, 2 * i,     a1 + i * F_DIM, b1 + i * F_DIM, 1, 0, out, asi, N);
        gemm_tc<<<grid, 256, SM_TOTAL>>>(1, 2 * i + 1, a2 + i * F_DIM, b2 + i * F_DIM, 0, 1, out, asi, N);
    }
    gemm_tc<<<grid, 256, SM_TOTAL>>>(0, 2 * R, oa, ob, 2, 0, out, asi, N); // 7
}

// round 10
// speedup vs baseline: 1.2142x; 1.2142x over previous
#include <cuda_runtime.h>
#include <cuda_bf16.h>
#include <math.h>
#include <stdint.h>

#define F_DIM 256
#define N_MAX 200000
#define B_MAX 4000
#define NPAD (N_MAX + 128)

// ---- scratch (device globals: allocation-free) ----
__device__ float g_kq[B_MAX * F_DIM];
__device__ float g_kb[B_MAX];
__device__ float g_vmol[B_MAX * F_DIM];
__device__ float g_a[N_MAX];
__device__ float g_part[(N_MAX + 7) / 8];
__device__ float g_inv[1];
__device__ int   g_ctr;
__device__ float g_H[(size_t)NPAD * F_DIM];
// ping-pong A operand buffers (stage parity) -- fixes R9 same-launch race
__device__ __nv_bfloat16 g_Ahi0[(size_t)NPAD * F_DIM];
__device__ __nv_bfloat16 g_Alo0[(size_t)NPAD * F_DIM];
__device__ __nv_bfloat16 g_Ahi1[(size_t)NPAD * F_DIM];
__device__ __nv_bfloat16 g_Alo1[(size_t)NPAD * F_DIM];
__device__ __nv_bfloat16 g_Whi[5 * F_DIM * F_DIM];
__device__ __nv_bfloat16 g_Wlo[5 * F_DIM * F_DIM];

// ============================================================
// helpers
// ============================================================
__device__ __forceinline__ uint32_t smem_u32(const void* p) {
    uint32_t a;
    asm("{ .reg .u64 t; cvta.to.shared.u64 t, %1; cvt.u32.u64 %0, t; }" : "=r"(a) : "l"(p));
    return a;
}
#define LDSM_X4(r, addr) \
    asm volatile("ldmatrix.sync.aligned.m8n8.x4.shared.b16 {%0,%1,%2,%3}, [%4];" \
        : "=r"((r)[0]), "=r"((r)[1]), "=r"((r)[2]), "=r"((r)[3]) : "r"(addr))
#define MMA_BF16(c, a, b) \
    asm volatile("mma.sync.aligned.m16n8k16.row.col.f32.bf16.bf16.f32 " \
        "{%0,%1,%2,%3}, {%4,%5,%6,%7}, {%8,%9}, {%0,%1,%2,%3};" \
        : "+f"((c)[0]), "+f"((c)[1]), "+f"((c)[2]), "+f"((c)[3]) \
        : "r"((a)[0]), "r"((a)[1]), "r"((a)[2]), "r"((a)[3]), "r"((b)[0]), "r"((b)[1]))
#define CP_ASYNC16(dst, src) \
    asm volatile("cp.async.cg.shared.global [%0], [%1], 16;" :: "r"(dst), "l"(src))
#define CP_COMMIT() asm volatile("cp.async.commit_group;" ::: "memory")
#define CP_WAIT0()  asm volatile("cp.async.wait_group 0;" ::: "memory")

__device__ __forceinline__ uint32_t pack2bf(float x, float y) {
    __nv_bfloat16 bx = __float2bfloat16_rn(x), by = __float2bfloat16_rn(y);
    return ((uint32_t)__bfloat16_as_ushort(by) << 16) | (uint32_t)__bfloat16_as_ushort(bx);
}
__device__ __forceinline__ void swsplit(float v, float al, float be, float& hi, float& lo) {
    float s  = be * v;
    float sw = al * s * (1.f / (1.f + __expf(-s)));
    __nv_bfloat16 bh = __float2bfloat16_rn(sw);
    hi = __bfloat162float(bh);
    lo = sw - hi;
}

// ============================================================
// K1: per-molecule prep (unchanged)
// ============================================================
__global__ void mol_prep(const float* __restrict__ E, const float* __restrict__ Wq,
                         const float* __restrict__ bq, const float* __restrict__ Wk,
                         const float* __restrict__ Wv, int B) {
    __shared__ float k_s[16][F_DIM];
    __shared__ float e_s[16][2], en_s[16][2];
    __shared__ float red[8];
    int tid = threadIdx.x;
    int b0  = blockIdx.x * 16;

    if (tid < 16) {
        int mol = b0 + tid;
        float Ev = (mol < B) ? E[mol] : 0.f;
        float e0 = fmaxf(Ev, 0.f), e1 = fmaxf(-Ev, 0.f);
        e_s[tid][0]  = e0;             e_s[tid][1]  = e1;
        en_s[tid][0] = fminf(e0, 1.f); en_s[tid][1] = fminf(e1, 1.f);
    }
    __syncthreads();

    float wk0 = Wk[tid * 2], wk1 = Wk[tid * 2 + 1];
    float wv0 = Wv[tid * 2], wv1 = Wv[tid * 2 + 1];
    #pragma unroll
    for (int b = 0; b < 16; b++) {
        float kv = en_s[b][0] * wk0 + en_s[b][1] * wk1;
        k_s[b][tid] = kv;
        int mol = b0 + b;
        if (mol < B) g_vmol[mol * F_DIM + tid] = e_s[b][0] * wv0 + e_s[b][1] * wv1;
    }
    __syncthreads();

    float acc[16];
    #pragma unroll
    for (int b = 0; b < 16; b++) acc[b] = 0.f;
    for (int f = 0; f < F_DIM; f++) {
        float w = Wq[f * F_DIM + tid];
        #pragma unroll
        for (int b = 0; b < 16; b++) acc[b] += k_s[b][f] * w;
    }
    #pragma unroll
    for (int b = 0; b < 16; b++) {
        int mol = b0 + b;
        if (mol < B) g_kq[mol * F_DIM + tid] = acc[b];
    }

    float bqv = bq[tid];
    int lane = tid & 31, wid = tid >> 5;
    for (int b = 0; b < 16; b++) {
        float v = k_s[b][tid] * bqv;
        #pragma unroll
        for (int o = 16; o > 0; o >>= 1) v += __shfl_down_sync(0xffffffffu, v, o);
        if (lane == 0) red[wid] = v;
        __syncthreads();
        if (tid == 0) {
            float s = 0.f;
            #pragma unroll
            for (int w = 0; w < 8; w++) s += red[w];
            int mol = b0 + b;
            if (mol < B) g_kb[mol] = s;
        }
        __syncthreads();
    }
}

// ============================================================
// K2: per-atom score + fused last-block global reduction -> g_inv
// ============================================================
__global__ void atom_score(const float* __restrict__ x, const int* __restrict__ idx, int N) {
    __shared__ float wsum[8];
    __shared__ int sdone;
    int tid = threadIdx.x, lane = tid & 31, wid = tid >> 5;
    int n = blockIdx.x * 8 + wid;
    float a = 0.f;
    if (n < N) {
        int m = idx[n];
        const float* xr = x    + (size_t)n * F_DIM;
        const float* kq = g_kq + (size_t)m * F_DIM;
        float s = 0.f;
        #pragma unroll
        for (int j = 0; j < 8; j++) { int c = lane + j * 32; s += xr[c] * kq[c]; }
        #pragma unroll
        for (int o = 16; o > 0; o >>= 1) s += __shfl_down_sync(0xffffffffu, s, o);
        if (lane == 0) {
            float d = (s + g_kb[m]) * 0.0625f;
            a = fmaxf(d, 0.f) + log1pf(expf(-fabsf(d)));
            g_a[n] = a;
        }
    }
    if (lane == 0) wsum[wid] = a;
    __syncthreads();
    if (tid == 0) {
        float t = 0.f;
        #pragma unroll
        for (int w = 0; w < 8; w++) t += wsum[w];
        g_part[blockIdx.x] = t;
        __threadfence();
        int c = atomicAdd(&g_ctr, 1);
        sdone = (c == (int)gridDim.x - 1);
    }
    __syncthreads();
    if (sdone) {
        __shared__ float red[256];
        float s = 0.f;
        int nparts = gridDim.x;
        for (int i = tid; i < nparts; i += 256) s += g_part[i];
        red[tid] = s;
        __syncthreads();
        for (int o = 128; o > 0; o >>= 1) {
            if (tid < o) red[tid] += red[tid + o];
            __syncthreads();
        }
        if (tid == 0) { g_inv[0] = 1.f / (red[0] + 1e-8f); g_ctr = 0; }
    }
}

// ============================================================
// K3: weight split + stage-0 A transform (into buffer 0)
// ============================================================
__global__ void prep_misc(const float* __restrict__ W1, const float* __restrict__ W2,
                          const float* __restrict__ Wout,
                          const float* __restrict__ a1, const float* __restrict__ b1,
                          const int* __restrict__ idx, int R, int wblocks, int N) {
    int tid = threadIdx.x;
    if ((int)blockIdx.x < wblocks) {
        int i = blockIdx.x * 256 + tid;
        int total = (2 * R + 1) * F_DIM * F_DIM;
        if (i >= total) return;
        int slot = i >> 16, j = i & 65535;
        const float* src = (slot == 2 * R) ? (Wout + j)
                         : (((slot & 1) ? W2 : W1) + (size_t)(slot >> 1) * 65536 + j);
        float w = *src;
        __nv_bfloat16 hi = __float2bfloat16_rn(w);
        __nv_bfloat16 lo = __float2bfloat16_rn(w - __bfloat162float(hi));
        g_Whi[i] = hi;
        g_Wlo[i] = lo;
        return;
    }
    int xb  = blockIdx.x - wblocks;
    int wid = tid >> 5, lane = tid & 31;
    int n = xb * 8 + wid;
    if (n >= N) return;
    int m = idx[n];
    float sc = g_a[n] * g_inv[0];
    const float* vp = g_vmol + (size_t)m * F_DIM;
    uint32_t* ahi = (uint32_t*)g_Ahi0 + (size_t)n * 128;
    uint32_t* alo = (uint32_t*)g_Alo0 + (size_t)n * 128;
    #pragma unroll
    for (int j = 0; j < 4; j++) {
        int u = lane + j * 32;
        int col = u * 2;
        float h0, l0, h1, l1;
        swsplit(sc * vp[col],     a1[col],     b1[col],     h0, l0);
        swsplit(sc * vp[col + 1], a1[col + 1], b1[col + 1], h1, l1);
        ahi[u] = pack2bf(h0, h1);
        alo[u] = pack2bf(l0, l1);
    }
}

// ============================================================
// K4: pure-MMA bf16 split-3 GEMM + transform epilogue.
// Reads A from buffer `abuf`, writes next-stage A to buffer abuf^1.
// ============================================================
#define BK 32
#define NCHUNK (F_DIM / BK)
#define PITCH 80
#define TILE (128 * PITCH)                 // 10240
#define SM_AL   0
#define SM_BE   1024
#define SM_RSC  2048
#define SM_RM   2560
#define SM_A    3072
#define SM_B    (3072 + 4 * TILE)
#define SM_TOTAL (SM_B + 4 * TILE)         // 84992
#define SM_STAGE SM_A
#define EPITCH 528

__global__ void __launch_bounds__(256, 2) gemm_tc(
    int slot, int abuf, const float* __restrict__ eal, const float* __restrict__ ebe,
    int eres, int ebase, int ewriteH, int eout,
    float* outp, const int* __restrict__ idx, int Nrows) {
    extern __shared__ char smem[];
    const uint32_t sb = smem_u32(smem);
    const int tid  = threadIdx.x;
    const int lane = tid & 31, wrp = tid >> 5;
    const int warpM = wrp >> 2, warpN = wrp & 3;   // 2 x 4
    const int m0 = blockIdx.x * 128;
    const int n0 = blockIdx.y * 128;

    float* sAl  = (float*)(smem + SM_AL);
    float* sBe  = (float*)(smem + SM_BE);
    float* sRsc = (float*)(smem + SM_RSC);
    int*   sRm  = (int*)  (smem + SM_RM);

    sAl[tid] = eal[tid];
    sBe[tid] = ebe[tid];
    {
        int r = tid >> 1;
        if ((tid & 1) == 0) {
            int grow = m0 + r;
            if (grow < Nrows) { sRsc[r] = g_a[grow] * g_inv[0]; sRm[r] = idx[grow]; }
            else              { sRsc[r] = 0.f; sRm[r] = 0; }
        }
    }
    __syncthreads();

    const __nv_bfloat16* Ahi = abuf ? g_Ahi1 : g_Ahi0;
    const __nv_bfloat16* Alo = abuf ? g_Alo1 : g_Alo0;
    __nv_bfloat16* WAhi = abuf ? g_Ahi0 : g_Ahi1;   // write side (next stage)
    __nv_bfloat16* WAlo = abuf ? g_Alo0 : g_Alo1;

    const __nv_bfloat16* Bbase[2] = { g_Whi + (size_t)slot * 65536 + (size_t)n0 * F_DIM,
                                      g_Wlo + (size_t)slot * 65536 + (size_t)n0 * F_DIM };

    float acc[4][4][4];
    #pragma unroll
    for (int i = 0; i < 4; i++)
        #pragma unroll
        for (int j = 0; j < 4; j++)
            #pragma unroll
            for (int l = 0; l < 4; l++) acc[i][j][l] = 0.f;

    auto cpAB = [&](int c, int db) {
        const int k0 = c * BK;
        #pragma unroll
        for (int i = 0; i < 4; i++) {
            int t = tid + i * 256;
            int sp = t >> 9, w = t & 511;
            int row = w >> 2, c16 = w & 3;
            const __nv_bfloat16* srcA = (sp ? Alo : Ahi)
                + (size_t)(m0 + row) * F_DIM + k0 + c16 * 8;
            CP_ASYNC16(sb + SM_A + (uint32_t)(db * 2 + sp) * TILE
                       + (uint32_t)row * PITCH + c16 * 16, srcA);
        }
        #pragma unroll
        for (int i = 0; i < 4; i++) {
            int t = tid + i * 256;
            int sp = t >> 9, w = t & 511;
            int row = w >> 2, c16 = w & 3;
            const __nv_bfloat16* srcB = Bbase[sp] + (size_t)row * F_DIM + k0 + c16 * 8;
            CP_ASYNC16(sb + SM_B + (uint32_t)(db * 2 + sp) * TILE
                       + (uint32_t)row * PITCH + c16 * 16, srcB);
        }
        CP_COMMIT();
    };

    cpAB(0, 0);
    CP_WAIT0();
    __syncthreads();

    const uint32_t aAddr0 = sb + SM_A + (uint32_t)(warpM * 64 + (lane & 15)) * PITCH
                          + ((lane >> 4) * 16);
    const uint32_t bAddr0 = sb + SM_B
                          + (uint32_t)(warpN * 32 + (lane & 7) + ((lane >> 4) << 3)) * PITCH
                          + (((lane >> 3) & 1) * 16);

    for (int c = 0; c < NCHUNK; c++) {
        const int db = c & 1;
        if (c + 1 < NCHUNK) cpAB(c + 1, db ^ 1);

        const uint32_t aB = aAddr0 + (uint32_t)(db * 2) * TILE;
        const uint32_t bB = bAddr0 + (uint32_t)(db * 2) * TILE;
        #pragma unroll
        for (int s = 0; s < 2; s++) {
            uint32_t bh[4][2], bl[4][2];
            #pragma unroll
            for (int ntp = 0; ntp < 2; ntp++) {
                uint32_t t4[4];
                uint32_t ab = bB + ntp * (16 * PITCH) + s * 32;
                LDSM_X4(t4, ab);
                bh[2*ntp][0] = t4[0]; bh[2*ntp][1] = t4[1];
                bh[2*ntp+1][0] = t4[2]; bh[2*ntp+1][1] = t4[3];
                LDSM_X4(t4, ab + TILE);
                bl[2*ntp][0] = t4[0]; bl[2*ntp][1] = t4[1];
                bl[2*ntp+1][0] = t4[2]; bl[2*ntp+1][1] = t4[3];
            }
            #pragma unroll
            for (int mt = 0; mt < 4; mt++) {
                uint32_t aa = aB + mt * (16 * PITCH) + s * 32;
                uint32_t ah[4], alr[4];
                LDSM_X4(ah, aa);
                LDSM_X4(alr, aa + TILE);
                #pragma unroll
                for (int nt = 0; nt < 4; nt++) {
                    MMA_BF16(acc[mt][nt], ah,  bh[nt]);
                    MMA_BF16(acc[mt][nt], ah,  bl[nt]);
                    MMA_BF16(acc[mt][nt], alr, bh[nt]);
                }
            }
        }
        CP_WAIT0();
        __syncthreads();
    }

    // ================= epilogue =================
    const int rbase = warpM * 64 + (lane >> 2);
    const int lcb   = warpN * 32 + (lane & 3) * 2;

    if (eout) {
        #pragma unroll
        for (int mt = 0; mt < 4; mt++)
            #pragma unroll
            for (int rh = 0; rh < 2; rh++) {
                int lr = rbase + mt * 16 + rh * 8;
                #pragma unroll
                for (int nt = 0; nt < 4; nt++) {
                    int lc = lcb + nt * 8;
                    *(float2*)(smem + SM_STAGE + lr * EPITCH + lc * 4)
                        = make_float2(acc[mt][nt][rh*2], acc[mt][nt][rh*2+1]);
                }
            }
        __syncthreads();
        #pragma unroll
        for (int i = 0; i < 32; i++) {
            int t = tid + i * 256;
            int row = t >> 6, cp = t & 63;
            int grow = m0 + row;
            if (grow < Nrows) {
                float2 v = *(float2*)(smem + SM_STAGE + row * EPITCH + cp * 8);
                *(float2*)(outp + (size_t)grow * F_DIM + n0 + cp * 2) = v;
            }
        }
        return;
    }

    #pragma unroll
    for (int mt = 0; mt < 4; mt++)
        #pragma unroll
        for (int rh = 0; rh < 2; rh++) {
            int lr = rbase + mt * 16 + rh * 8;
            int grow = m0 + lr;
            #pragma unroll
            for (int nt = 0; nt < 4; nt++) {
                int lc = lcb + nt * 8;
                int gcol = n0 + lc;
                float v0 = acc[mt][nt][rh*2], v1 = acc[mt][nt][rh*2+1];
                if (eres) {
                    if (ebase == 0) {
                        float sc = sRsc[lr];
                        const float* vp = g_vmol + (size_t)sRm[lr] * F_DIM + gcol;
                        v0 += sc * vp[0]; v1 += sc * vp[1];
                    } else {
                        float2 o = *(const float2*)(g_H + (size_t)grow * F_DIM + gcol);
                        v0 += o.x; v1 += o.y;
                    }
                    if (ewriteH && grow < Nrows)
                        *(float2*)(g_H + (size_t)grow * F_DIM + gcol) = make_float2(v0, v1);
                }
                float h0, l0, h1, l1;
                swsplit(v0, sAl[gcol],     sBe[gcol],     h0, l0);
                swsplit(v1, sAl[gcol + 1], sBe[gcol + 1], h1, l1);
                *(uint2*)(smem + SM_STAGE + lr * EPITCH + lc * 4)
                    = make_uint2(pack2bf(h0, h1), pack2bf(l0, l1));
            }
        }
    __syncthreads();
    uint32_t* ahi = (uint32_t*)WAhi;
    uint32_t* alo = (uint32_t*)WAlo;
    #pragma unroll
    for (int i = 0; i < 32; i++) {
        int t = tid + i * 256;
        int row = t >> 6, cp = t & 63;
        int grow = m0 + row;
        if (grow < Nrows) {
            uint2 v = *(uint2*)(smem + SM_STAGE + row * EPITCH + cp * 8);
            size_t o = (size_t)grow * 128 + (n0 >> 1) + cp;
            ahi[o] = v.x;
            alo[o] = v.y;
        }
    }
}

// ============================================================
extern "C" void kernel_launch(void* const* d_in, const int* in_sizes, int n_in,
                              void* d_out, int out_size) {
    const float* x    = (const float*)d_in[0];
    const float* E    = (const float*)d_in[1];
    const int*   asi  = (const int*)  d_in[2];
    const float* Wq   = (const float*)d_in[3];
    const float* bq   = (const float*)d_in[4];
    const float* Wk   = (const float*)d_in[5];
    const float* Wv   = (const float*)d_in[6];
    const float* W1   = (const float*)d_in[7];
    const float* W2   = (const float*)d_in[8];
    const float* a1   = (const float*)d_in[9];
    const float* b1   = (const float*)d_in[10];
    const float* a2   = (const float*)d_in[11];
    const float* b2   = (const float*)d_in[12];
    const float* oa   = (const float*)d_in[13];
    const float* ob   = (const float*)d_in[14];
    const float* Wout = (const float*)d_in[15];

    int B = in_sizes[1];
    int N = in_sizes[2];
    int R = in_sizes[7] / (F_DIM * F_DIM);
    float* out = (float*)d_out;

    cudaFuncSetAttribute(gemm_tc, cudaFuncAttributeMaxDynamicSharedMemorySize, SM_TOTAL);

    mol_prep<<<(B + 15) / 16, 256>>>(E, Wq, bq, Wk, Wv, B);              // 0

    int gS = (N + 7) / 8;
    atom_score<<<gS, 256>>>(x, asi, N);                                   // 1

    int wblocks = (2 * R + 1) * F_DIM;
    int xblocks = (N + 7) / 8;
    prep_misc<<<wblocks + xblocks, 256>>>(W1, W2, Wout, a1, b1, asi, R, wblocks, N);  // 2

    dim3 grid((N + 127) / 128, 2);
    int abuf = 0;
    for (int i = 0; i < R; i++) {
        gemm_tc<<<grid, 256, SM_TOTAL>>>(2 * i, abuf, a2 + i * F_DIM, b2 + i * F_DIM,
                                         0, 0, 0, 0, out, asi, N);
        abuf ^= 1;
        const float* nal = (i + 1 < R) ? (a1 + (i + 1) * F_DIM) : oa;
        const float* nbe = (i + 1 < R) ? (b1 + (i + 1) * F_DIM) : ob;
        gemm_tc<<<grid, 256, SM_TOTAL>>>(2 * i + 1, abuf, nal, nbe,
                                         1, (i == 0) ? 0 : 1, (i < R - 1) ? 1 : 0, 0,
                                         out, asi, N);
        abuf ^= 1;
    }
    gemm_tc<<<grid, 256, SM_TOTAL>>>(2 * R, abuf, oa, ob, 0, 0, 0, 1, out, asi, N);
}